// round 14
// baseline (speedup 1.0000x reference)
#include <cuda_runtime.h>
#include <cuda_fp16.h>
#include <cstdint>

#define NTOK   64
#define DIM    512
#define NHEAD  16
#define HDIM   32
#define NWIN   64
#define BWTOT  1024
#define SCALE  0.17677669529663687f
#define KDIM   512

__device__ __half g_xh [BWTOT * NTOK * DIM];
__device__ __half g_qkv[3 * BWTOT * NHEAD * NTOK * HDIM];
__device__ __half g_att[BWTOT * NTOK * DIM];
__device__ __half g_wq [3 * DIM * DIM];
__device__ __half g_wp [DIM * DIM];
__device__ float  g_bt [NHEAD * NTOK * NTOK];   // gathered rel-pos bias, 256 KB (L2-hot)

// ---------------------------------------------------------------------------
__device__ __forceinline__ uint32_t smem_u32(const void* p) {
    uint32_t a;
    asm("{ .reg .u64 t; cvta.to.shared.u64 t, %1; cvt.u32.u64 %0, t; }" : "=r"(a) : "l"(p));
    return a;
}
__device__ __forceinline__ void cp16(uint32_t dst, const void* src) {
    asm volatile("cp.async.cg.shared.global [%0], [%1], 16;" :: "r"(dst), "l"(src));
}
#define CP_COMMIT() asm volatile("cp.async.commit_group;" ::: "memory")
#define CP_WAIT2()  asm volatile("cp.async.wait_group 2;" ::: "memory")
#define CP_WAIT1()  asm volatile("cp.async.wait_group 1;" ::: "memory")
#define CP_WAIT0()  asm volatile("cp.async.wait_group 0;" ::: "memory")

__device__ __forceinline__ void mma_f16(float* c, const unsigned* a, const unsigned* b) {
    asm volatile(
        "mma.sync.aligned.m16n8k16.row.col.f32.f16.f16.f32 "
        "{%0,%1,%2,%3}, {%4,%5,%6,%7}, {%8,%9}, {%0,%1,%2,%3};"
        : "+f"(c[0]), "+f"(c[1]), "+f"(c[2]), "+f"(c[3])
        : "r"(a[0]), "r"(a[1]), "r"(a[2]), "r"(a[3]), "r"(b[0]), "r"(b[1]));
}
__device__ __forceinline__ void ldsm4(unsigned* r, uint32_t a) {
    asm volatile("ldmatrix.sync.aligned.m8n8.x4.shared.b16 {%0,%1,%2,%3}, [%4];"
                 : "=r"(r[0]), "=r"(r[1]), "=r"(r[2]), "=r"(r[3]) : "r"(a));
}

// ---------------------------------------------------------------------------
// Prepasses
// ---------------------------------------------------------------------------
__global__ void h_kernel(const float* __restrict__ src, __half* __restrict__ dst, int n4)
{
    const int i = blockIdx.x * blockDim.x + threadIdx.x;
    if (i < n4) {
        float4 v = ((const float4*)src)[i];
        ((__half2*)dst)[2 * i]     = __floats2half2_rn(v.x, v.y);
        ((__half2*)dst)[2 * i + 1] = __floats2half2_rn(v.z, v.w);
    }
}

#define WQ4 (3 * DIM * DIM / 4)
#define WP4 (DIM * DIM / 4)
__global__ void w_kernel(const float* __restrict__ qkv_w, const float* __restrict__ proj_w)
{
    const int i = blockIdx.x * blockDim.x + threadIdx.x;
    const float4 v = (i < WQ4) ? ((const float4*)qkv_w)[i]
                               : ((const float4*)proj_w)[i - WQ4];
    __half2* dst = (i < WQ4) ? (__half2*)g_wq + 2 * i
                             : (__half2*)g_wp + 2 * (i - WQ4);
    dst[0] = __floats2half2_rn(v.x, v.y);
    dst[1] = __floats2half2_rn(v.z, v.w);
}

__global__ void bt_kernel(const float* __restrict__ btab, const int* __restrict__ ridx)
{
    const int idx = blockIdx.x * blockDim.x + threadIdx.x;
    const int rc = idx & 4095;
    const int h  = idx >> 12;
    g_bt[idx] = btab[ridx[rc] * NHEAD + h];
}

// ---------------------------------------------------------------------------
// fp16 mma.sync GEMM (round-9 config): 128 threads, 4 warps (2x2 of 64x64),
// block tile 128x128, BK=64, 3-stage cp.async, ldmatrix, XOR swizzle, 2 CTAs/SM.
// ---------------------------------------------------------------------------
#define BKH 64
#define STG 3
#define STAGE_ROWS 128
#define GEMM_SMEM (STG * 2 * STAGE_ROWS * BKH * 2)   // 98304

template<int MODE>
__global__ __launch_bounds__(128, 2) void tc_gemm(
    const float* __restrict__ bias, float* __restrict__ C)
{
    extern __shared__ char smh[];
    const uint32_t sA = smem_u32(smh);
    const uint32_t sB = sA + STG * STAGE_ROWS * 128;

    const int tid  = threadIdx.x;
    const int warp = tid >> 5;
    const int lane = tid & 31;
    const int g    = lane >> 2;
    const int tg   = lane & 3;
    const int wm   = (warp >> 1) * 64;
    const int wn   = (warp & 1) * 64;
    const int bm = blockIdx.y, bn = blockIdx.x;

    const __half* Ap = (MODE == 0 ? g_xh : g_att) + (size_t)bm * 128 * KDIM;
    const __half* Bp = (MODE == 0 ? g_wq : g_wp) + (size_t)bn * 128 * KDIM;

    const int mi    = lane >> 3;
    const int l7    = lane & 7;
    const int arow  = wm + (mi & 1) * 8 + l7;
    const int achk  = mi >> 1;
    const int brow  = wn + (mi >> 1) * 8 + l7;
    const int bchk  = mi & 1;

    float acc[4][8][4];
#pragma unroll
    for (int i = 0; i < 4; i++)
#pragma unroll
        for (int j = 0; j < 8; j++)
#pragma unroll
            for (int r = 0; r < 4; r++) acc[i][j][r] = 0.0f;

    auto issue = [&](int ks) {
        const int k0 = ks * BKH;
        const int buf = ks % STG;
#pragma unroll
        for (int t = 0; t < 8; t++) {
            const int id = tid + t * 128;
            const int r = id >> 3, c = id & 7;
            const uint32_t off = ((buf * STAGE_ROWS + r) * 8 + (c ^ (r & 7))) * 16;
            cp16(sA + off, Ap + (size_t)r * KDIM + k0 + c * 8);
            cp16(sB + off, Bp + (size_t)r * KDIM + k0 + c * 8);
        }
        CP_COMMIT();
    };

    issue(0); issue(1);
    for (int ks = 0; ks < 8; ks++) {
        if (ks < 6) { issue(ks + 2); CP_WAIT2(); }
        else if (ks == 6) { CP_WAIT1(); }
        else { CP_WAIT0(); }
        __syncthreads();

        const int bo = (ks % STG) * STAGE_ROWS;
#pragma unroll
        for (int kk = 0; kk < 4; kk++) {
            unsigned af[4][4], bf[8][2];
#pragma unroll
            for (int mt = 0; mt < 4; mt++) {
                const int r = bo + arow + mt * 16;
                ldsm4(af[mt], sA + (r * 8 + ((kk * 2 + achk) ^ l7)) * 16);
            }
#pragma unroll
            for (int j = 0; j < 4; j++) {
                const int r = bo + brow + j * 16;
                ldsm4(&bf[2 * j][0], sB + (r * 8 + ((kk * 2 + bchk) ^ l7)) * 16);
            }
#pragma unroll
            for (int mt = 0; mt < 4; mt++)
#pragma unroll
                for (int nt = 0; nt < 8; nt++)
                    mma_f16(acc[mt][nt], af[mt], bf[nt]);
        }
        __syncthreads();
    }

#pragma unroll
    for (int mt = 0; mt < 4; mt++) {
#pragma unroll
        for (int nt = 0; nt < 8; nt++) {
#pragma unroll
            for (int half = 0; half < 2; half++) {
                const int m   = bm * 128 + wm + mt * 16 + g + half * 8;
                const int col = bn * 128 + wn + nt * 8 + 2 * tg;
                const float v0 = acc[mt][nt][half * 2 + 0] + bias[col];
                const float v1 = acc[mt][nt][half * 2 + 1] + bias[col + 1];
                if (MODE == 0) {
                    const int part = col >> 9;
                    const int h    = (col >> 5) & 15;
                    const int d    = col & 31;
                    const int bw   = m >> 6;
                    const int n    = m & 63;
                    __half* dst = &g_qkv[(((size_t)part * BWTOT + bw) * NHEAD + h)
                                         * (NTOK * HDIM) + n * HDIM + d];
                    *(__half2*)dst = __floats2half2_rn(v0, v1);
                } else {
                    *(float2*)&C[(size_t)m * DIM + col] = make_float2(v0, v1);
                }
            }
        }
    }
}

// ---------------------------------------------------------------------------
// fp16 tensor-core attention: one block per (window, head-pair). 256 threads,
// warps 0-3 -> head 2*hp, warps 4-7 -> head 2*hp+1. mask[w] L2-hot, shared
// across the pair; bt[h] L2-hot.
// ---------------------------------------------------------------------------
__global__ __launch_bounds__(256) void attn_kernel(const float* __restrict__ mask)
{
    __shared__ __half sq[2][64][40], sk[2][64][40];
    __shared__ __half svt[2][32][72];
    __shared__ __half sp[2][64][72];

    const int tid  = threadIdx.x;
    const int hw   = tid >> 7;          // head within block (0/1)
    const int ltid = tid & 127;
    const int warp = ltid >> 5;         // warp within head (0..3)
    const int lane = tid & 31;
    const int g    = lane >> 2;
    const int tg   = lane & 3;
    const int bw = blockIdx.x >> 3;
    const int h  = (blockIdx.x & 7) * 2 + hw;

    const __half2* qp = (const __half2*)(g_qkv + ((size_t)bw * NHEAD + h) * (NTOK * HDIM));
    const __half2* kp = qp + (size_t)BWTOT * NHEAD * NTOK * HDIM / 2;
    const __half2* vp = kp + (size_t)BWTOT * NHEAD * NTOK * HDIM / 2;

    for (int i = ltid; i < NTOK * HDIM / 2; i += 128) {
        const int r = i >> 4, d = (i & 15) * 2;
        float2 q2 = __half22float2(qp[i]);
        *(__half2*)&sq[hw][r][d] = __floats2half2_rn(q2.x * SCALE, q2.y * SCALE);
        *(__half2*)&sk[hw][r][d] = kp[i];
        __half2 v2 = vp[i];
        svt[hw][d][r]     = __low2half(v2);
        svt[hw][d + 1][r] = __high2half(v2);
    }
    __syncthreads();

    const int row0 = warp * 16;
    const int r1 = row0 + g, r2 = row0 + g + 8;

    float c[8][4];
#pragma unroll
    for (int nt = 0; nt < 8; nt++)
#pragma unroll
        for (int r = 0; r < 4; r++) c[nt][r] = 0.0f;

#pragma unroll
    for (int kk = 0; kk < 2; kk++) {
        const int k0 = kk * 16;
        unsigned af[4];
        af[0] = *(const unsigned*)&sq[hw][r1][k0 + 2 * tg];
        af[1] = *(const unsigned*)&sq[hw][r2][k0 + 2 * tg];
        af[2] = *(const unsigned*)&sq[hw][r1][k0 + 2 * tg + 8];
        af[3] = *(const unsigned*)&sq[hw][r2][k0 + 2 * tg + 8];
#pragma unroll
        for (int nt = 0; nt < 8; nt++) {
            unsigned bf[2];
            bf[0] = *(const unsigned*)&sk[hw][nt * 8 + g][k0 + 2 * tg];
            bf[1] = *(const unsigned*)&sk[hw][nt * 8 + g][k0 + 2 * tg + 8];
            mma_f16(c[nt], af, bf);
        }
    }

    // ---- + bias (g_bt[h]) + mask (mask[w]) — both L2-hot ----
    const float* btp = g_bt + (size_t)h * 4096;
    const float* mkp = mask + (size_t)(bw & (NWIN - 1)) * 4096;
#pragma unroll
    for (int nt = 0; nt < 8; nt++) {
        const int cc = nt * 8 + 2 * tg;
        float2 t1 = *(const float2*)&btp[r1 * 64 + cc];
        float2 t2 = *(const float2*)&btp[r2 * 64 + cc];
        float2 u1 = *(const float2*)&mkp[r1 * 64 + cc];
        float2 u2 = *(const float2*)&mkp[r2 * 64 + cc];
        c[nt][0] += t1.x + u1.x; c[nt][1] += t1.y + u1.y;
        c[nt][2] += t2.x + u2.x; c[nt][3] += t2.y + u2.y;
    }

    float m1 = -1e30f, m2 = -1e30f;
#pragma unroll
    for (int nt = 0; nt < 8; nt++) {
        m1 = fmaxf(m1, fmaxf(c[nt][0], c[nt][1]));
        m2 = fmaxf(m2, fmaxf(c[nt][2], c[nt][3]));
    }
#pragma unroll
    for (int off = 1; off < 4; off <<= 1) {
        m1 = fmaxf(m1, __shfl_xor_sync(0xffffffffu, m1, off));
        m2 = fmaxf(m2, __shfl_xor_sync(0xffffffffu, m2, off));
    }
    float s1 = 0.0f, s2 = 0.0f;
#pragma unroll
    for (int nt = 0; nt < 8; nt++) {
        c[nt][0] = __expf(c[nt][0] - m1);
        c[nt][1] = __expf(c[nt][1] - m1);
        c[nt][2] = __expf(c[nt][2] - m2);
        c[nt][3] = __expf(c[nt][3] - m2);
        s1 += c[nt][0] + c[nt][1];
        s2 += c[nt][2] + c[nt][3];
    }
#pragma unroll
    for (int off = 1; off < 4; off <<= 1) {
        s1 += __shfl_xor_sync(0xffffffffu, s1, off);
        s2 += __shfl_xor_sync(0xffffffffu, s2, off);
    }
    const float inv1 = 1.0f / s1, inv2 = 1.0f / s2;
#pragma unroll
    for (int nt = 0; nt < 8; nt++) {
        const int cc = nt * 8 + 2 * tg;
        *(__half2*)&sp[hw][r1][cc] = __floats2half2_rn(c[nt][0] * inv1, c[nt][1] * inv1);
        *(__half2*)&sp[hw][r2][cc] = __floats2half2_rn(c[nt][2] * inv2, c[nt][3] * inv2);
    }
    __syncthreads();

    float o[4][4];
#pragma unroll
    for (int nt = 0; nt < 4; nt++)
#pragma unroll
        for (int r = 0; r < 4; r++) o[nt][r] = 0.0f;

#pragma unroll
    for (int kk = 0; kk < 4; kk++) {
        const int k0 = kk * 16;
        unsigned af[4];
        af[0] = *(const unsigned*)&sp[hw][r1][k0 + 2 * tg];
        af[1] = *(const unsigned*)&sp[hw][r2][k0 + 2 * tg];
        af[2] = *(const unsigned*)&sp[hw][r1][k0 + 2 * tg + 8];
        af[3] = *(const unsigned*)&sp[hw][r2][k0 + 2 * tg + 8];
#pragma unroll
        for (int nt = 0; nt < 4; nt++) {
            unsigned bf[2];
            bf[0] = *(const unsigned*)&svt[hw][nt * 8 + g][k0 + 2 * tg];
            bf[1] = *(const unsigned*)&svt[hw][nt * 8 + g][k0 + 2 * tg + 8];
            mma_f16(o[nt], af, bf);
        }
    }

#pragma unroll
    for (int nt = 0; nt < 4; nt++) {
        const int col = h * HDIM + nt * 8 + 2 * tg;
        *(__half2*)&g_att[((size_t)bw * NTOK + r1) * DIM + col] =
            __floats2half2_rn(o[nt][0], o[nt][1]);
        *(__half2*)&g_att[((size_t)bw * NTOK + r2) * DIM + col] =
            __floats2half2_rn(o[nt][2], o[nt][3]);
    }
}

// ---------------------------------------------------------------------------
extern "C" void kernel_launch(void* const* d_in, const int* in_sizes, int n_in,
                              void* d_out, int out_size)
{
    const float* x      = (const float*)d_in[0];
    const float* mask   = (const float*)d_in[1];
    const float* qkv_w  = (const float*)d_in[2];
    const float* qkv_b  = (const float*)d_in[3];
    const float* btab   = (const float*)d_in[4];
    const float* proj_w = (const float*)d_in[5];
    const float* proj_b = (const float*)d_in[6];
    const int*   ridx   = (const int*)d_in[7];
    float* out = (float*)d_out;

    static bool configured = false;
    if (!configured) {
        cudaFuncSetAttribute(tc_gemm<0>, cudaFuncAttributeMaxDynamicSharedMemorySize, GEMM_SMEM);
        cudaFuncSetAttribute(tc_gemm<1>, cudaFuncAttributeMaxDynamicSharedMemorySize, GEMM_SMEM);
        configured = true;
    }

    __half* xh; cudaGetSymbolAddress((void**)&xh, g_xh);

    // prepasses
    w_kernel<<<(WQ4 + WP4 + 255) / 256, 256>>>(qkv_w, proj_w);
    bt_kernel<<<NHEAD * 4096 / 256, 256>>>(btab, ridx);
    h_kernel<<<(BWTOT * NTOK * DIM / 4 + 255) / 256, 256>>>(x, xh, BWTOT * NTOK * DIM / 4);

    // QKV: (65536 x 512) @ (512 x 1536)^T
    tc_gemm<0><<<dim3(12, 512), 128, GEMM_SMEM>>>(qkv_b, nullptr);
    // attention: one block per (window, head-pair)
    attn_kernel<<<BWTOT * (NHEAD / 2), 256>>>(mask);
    // proj: (65536 x 512) @ (512 x 512)^T
    tc_gemm<1><<<dim3(4, 512), 128, GEMM_SMEM>>>(proj_b, out);
}

// round 16
// speedup vs baseline: 1.0071x; 1.0071x over previous
#include <cuda_runtime.h>
#include <cuda_fp16.h>
#include <cstdint>

#define NTOK   64
#define DIM    512
#define NHEAD  16
#define HDIM   32
#define NWIN   64
#define BWTOT  1024
#define SCALE  0.17677669529663687f
#define KDIM   512

__device__ __half g_xh [BWTOT * NTOK * DIM];
__device__ __half g_qkv[3 * BWTOT * NHEAD * NTOK * HDIM];
__device__ __half g_att[BWTOT * NTOK * DIM];
__device__ __half g_wq [3 * DIM * DIM];
__device__ __half g_wp [DIM * DIM];
__device__ float  g_bt [NHEAD * NTOK * NTOK];   // gathered rel-pos bias, 256 KB (L2-hot)

// ---------------------------------------------------------------------------
__device__ __forceinline__ uint32_t smem_u32(const void* p) {
    uint32_t a;
    asm("{ .reg .u64 t; cvta.to.shared.u64 t, %1; cvt.u32.u64 %0, t; }" : "=r"(a) : "l"(p));
    return a;
}
__device__ __forceinline__ void cp16(uint32_t dst, const void* src) {
    asm volatile("cp.async.cg.shared.global [%0], [%1], 16;" :: "r"(dst), "l"(src));
}
#define CP_COMMIT() asm volatile("cp.async.commit_group;" ::: "memory")
#define CP_WAIT1()  asm volatile("cp.async.wait_group 1;" ::: "memory")
#define CP_WAIT0()  asm volatile("cp.async.wait_group 0;" ::: "memory")

__device__ __forceinline__ void mma_f16(float* c, const unsigned* a, const unsigned* b) {
    asm volatile(
        "mma.sync.aligned.m16n8k16.row.col.f32.f16.f16.f32 "
        "{%0,%1,%2,%3}, {%4,%5,%6,%7}, {%8,%9}, {%0,%1,%2,%3};"
        : "+f"(c[0]), "+f"(c[1]), "+f"(c[2]), "+f"(c[3])
        : "r"(a[0]), "r"(a[1]), "r"(a[2]), "r"(a[3]), "r"(b[0]), "r"(b[1]));
}
__device__ __forceinline__ void ldsm4(unsigned* r, uint32_t a) {
    asm volatile("ldmatrix.sync.aligned.m8n8.x4.shared.b16 {%0,%1,%2,%3}, [%4];"
                 : "=r"(r[0]), "=r"(r[1]), "=r"(r[2]), "=r"(r[3]) : "r"(a));
}

// ---------------------------------------------------------------------------
// Prepasses
// ---------------------------------------------------------------------------
__global__ void h_kernel(const float* __restrict__ src, __half* __restrict__ dst, int n4)
{
    const int i = blockIdx.x * blockDim.x + threadIdx.x;
    if (i < n4) {
        float4 v = ((const float4*)src)[i];
        ((__half2*)dst)[2 * i]     = __floats2half2_rn(v.x, v.y);
        ((__half2*)dst)[2 * i + 1] = __floats2half2_rn(v.z, v.w);
    }
}

// merged: weight conversion (qkv_w -> g_wq, proj_w -> g_wp) + bias gather (g_bt)
#define WQ4 (3 * DIM * DIM / 4)          // 196608
#define WP4 (DIM * DIM / 4)              // 65536
#define BT4 (NHEAD * NTOK * NTOK / 4)    // 16384
__global__ void prep_kernel(const float* __restrict__ qkv_w, const float* __restrict__ proj_w,
                            const float* __restrict__ btab, const int* __restrict__ ridx)
{
    const int i = blockIdx.x * blockDim.x + threadIdx.x;
    if (i < WQ4) {
        const float4 v = ((const float4*)qkv_w)[i];
        ((__half2*)g_wq)[2 * i]     = __floats2half2_rn(v.x, v.y);
        ((__half2*)g_wq)[2 * i + 1] = __floats2half2_rn(v.z, v.w);
    } else if (i < WQ4 + WP4) {
        const int j = i - WQ4;
        const float4 v = ((const float4*)proj_w)[j];
        ((__half2*)g_wp)[2 * j]     = __floats2half2_rn(v.x, v.y);
        ((__half2*)g_wp)[2 * j + 1] = __floats2half2_rn(v.z, v.w);
    } else if (i < WQ4 + WP4 + BT4) {
        const int j = (i - WQ4 - WP4) * 4;
#pragma unroll
        for (int k = 0; k < 4; k++) {
            const int idx = j + k;
            g_bt[idx] = btab[ridx[idx & 4095] * NHEAD + (idx >> 12)];
        }
    }
}

// ---------------------------------------------------------------------------
// fp16 mma.sync GEMM: 128 threads, 4 warps (2x2 of 64x64), block tile 128x128,
// BK=64, 3-stage cp.async, ldmatrix, XOR swizzle, 2 CTAs/SM.
// Single barrier per stage: wait -> sync -> issue -> compute.
// ---------------------------------------------------------------------------
#define BKH 64
#define STG 3
#define STAGE_ROWS 128
#define GEMM_SMEM (STG * 2 * STAGE_ROWS * BKH * 2)   // 98304

template<int MODE>
__global__ __launch_bounds__(128, 2) void tc_gemm(
    const float* __restrict__ bias, float* __restrict__ C)
{
    extern __shared__ char smh[];
    const uint32_t sA = smem_u32(smh);
    const uint32_t sB = sA + STG * STAGE_ROWS * 128;

    const int tid  = threadIdx.x;
    const int warp = tid >> 5;
    const int lane = tid & 31;
    const int g    = lane >> 2;
    const int tg   = lane & 3;
    const int wm   = (warp >> 1) * 64;
    const int wn   = (warp & 1) * 64;
    const int bm = blockIdx.y, bn = blockIdx.x;

    const __half* Ap = (MODE == 0 ? g_xh : g_att) + (size_t)bm * 128 * KDIM;
    const __half* Bp = (MODE == 0 ? g_wq : g_wp) + (size_t)bn * 128 * KDIM;

    const int mi    = lane >> 3;
    const int l7    = lane & 7;
    const int arow  = wm + (mi & 1) * 8 + l7;
    const int achk  = mi >> 1;
    const int brow  = wn + (mi >> 1) * 8 + l7;
    const int bchk  = mi & 1;

    float acc[4][8][4];
#pragma unroll
    for (int i = 0; i < 4; i++)
#pragma unroll
        for (int j = 0; j < 8; j++)
#pragma unroll
            for (int r = 0; r < 4; r++) acc[i][j][r] = 0.0f;

    auto issue = [&](int ks) {
        const int k0 = ks * BKH;
        const int buf = ks % STG;
#pragma unroll
        for (int t = 0; t < 8; t++) {
            const int id = tid + t * 128;
            const int r = id >> 3, c = id & 7;
            const uint32_t off = ((buf * STAGE_ROWS + r) * 8 + (c ^ (r & 7))) * 16;
            cp16(sA + off, Ap + (size_t)r * KDIM + k0 + c * 8);
            cp16(sB + off, Bp + (size_t)r * KDIM + k0 + c * 8);
        }
        CP_COMMIT();
    };

    issue(0); issue(1);
    for (int ks = 0; ks < 8; ks++) {
        if (ks < 7) { CP_WAIT1(); } else { CP_WAIT0(); }
        __syncthreads();
        if (ks < 6) issue(ks + 2);

        const int bo = (ks % STG) * STAGE_ROWS;
#pragma unroll
        for (int kk = 0; kk < 4; kk++) {
            unsigned af[4][4], bf[8][2];
#pragma unroll
            for (int mt = 0; mt < 4; mt++) {
                const int r = bo + arow + mt * 16;
                ldsm4(af[mt], sA + (r * 8 + ((kk * 2 + achk) ^ l7)) * 16);
            }
#pragma unroll
            for (int j = 0; j < 4; j++) {
                const int r = bo + brow + j * 16;
                ldsm4(&bf[2 * j][0], sB + (r * 8 + ((kk * 2 + bchk) ^ l7)) * 16);
            }
#pragma unroll
            for (int mt = 0; mt < 4; mt++)
#pragma unroll
                for (int nt = 0; nt < 8; nt++)
                    mma_f16(acc[mt][nt], af[mt], bf[nt]);
        }
    }

#pragma unroll
    for (int mt = 0; mt < 4; mt++) {
#pragma unroll
        for (int nt = 0; nt < 8; nt++) {
#pragma unroll
            for (int half = 0; half < 2; half++) {
                const int m   = bm * 128 + wm + mt * 16 + g + half * 8;
                const int col = bn * 128 + wn + nt * 8 + 2 * tg;
                const float v0 = acc[mt][nt][half * 2 + 0] + bias[col];
                const float v1 = acc[mt][nt][half * 2 + 1] + bias[col + 1];
                if (MODE == 0) {
                    const int part = col >> 9;
                    const int h    = (col >> 5) & 15;
                    const int d    = col & 31;
                    const int bw   = m >> 6;
                    const int n    = m & 63;
                    __half* dst = &g_qkv[(((size_t)part * BWTOT + bw) * NHEAD + h)
                                         * (NTOK * HDIM) + n * HDIM + d];
                    *(__half2*)dst = __floats2half2_rn(v0, v1);
                } else {
                    *(float2*)&C[(size_t)m * DIM + col] = make_float2(v0, v1);
                }
            }
        }
    }
}

// ---------------------------------------------------------------------------
// fp16 tensor-core attention: one block per (window, head-pair). 256 threads.
// ---------------------------------------------------------------------------
__global__ __launch_bounds__(256) void attn_kernel(const float* __restrict__ mask)
{
    __shared__ __half sq[2][64][40], sk[2][64][40];
    __shared__ __half svt[2][32][72];
    __shared__ __half sp[2][64][72];

    const int tid  = threadIdx.x;
    const int hw   = tid >> 7;
    const int ltid = tid & 127;
    const int warp = ltid >> 5;
    const int lane = tid & 31;
    const int g    = lane >> 2;
    const int tg   = lane & 3;
    const int bw = blockIdx.x >> 3;
    const int h  = (blockIdx.x & 7) * 2 + hw;

    const __half2* qp = (const __half2*)(g_qkv + ((size_t)bw * NHEAD + h) * (NTOK * HDIM));
    const __half2* kp = qp + (size_t)BWTOT * NHEAD * NTOK * HDIM / 2;
    const __half2* vp = kp + (size_t)BWTOT * NHEAD * NTOK * HDIM / 2;

    for (int i = ltid; i < NTOK * HDIM / 2; i += 128) {
        const int r = i >> 4, d = (i & 15) * 2;
        float2 q2 = __half22float2(qp[i]);
        *(__half2*)&sq[hw][r][d] = __floats2half2_rn(q2.x * SCALE, q2.y * SCALE);
        *(__half2*)&sk[hw][r][d] = kp[i];
        __half2 v2 = vp[i];
        svt[hw][d][r]     = __low2half(v2);
        svt[hw][d + 1][r] = __high2half(v2);
    }
    __syncthreads();

    const int row0 = warp * 16;
    const int r1 = row0 + g, r2 = row0 + g + 8;

    float c[8][4];
#pragma unroll
    for (int nt = 0; nt < 8; nt++)
#pragma unroll
        for (int r = 0; r < 4; r++) c[nt][r] = 0.0f;

#pragma unroll
    for (int kk = 0; kk < 2; kk++) {
        const int k0 = kk * 16;
        unsigned af[4];
        af[0] = *(const unsigned*)&sq[hw][r1][k0 + 2 * tg];
        af[1] = *(const unsigned*)&sq[hw][r2][k0 + 2 * tg];
        af[2] = *(const unsigned*)&sq[hw][r1][k0 + 2 * tg + 8];
        af[3] = *(const unsigned*)&sq[hw][r2][k0 + 2 * tg + 8];
#pragma unroll
        for (int nt = 0; nt < 8; nt++) {
            unsigned bf[2];
            bf[0] = *(const unsigned*)&sk[hw][nt * 8 + g][k0 + 2 * tg];
            bf[1] = *(const unsigned*)&sk[hw][nt * 8 + g][k0 + 2 * tg + 8];
            mma_f16(c[nt], af, bf);
        }
    }

    const float* btp = g_bt + (size_t)h * 4096;
    const float* mkp = mask + (size_t)(bw & (NWIN - 1)) * 4096;
#pragma unroll
    for (int nt = 0; nt < 8; nt++) {
        const int cc = nt * 8 + 2 * tg;
        float2 t1 = *(const float2*)&btp[r1 * 64 + cc];
        float2 t2 = *(const float2*)&btp[r2 * 64 + cc];
        float2 u1 = *(const float2*)&mkp[r1 * 64 + cc];
        float2 u2 = *(const float2*)&mkp[r2 * 64 + cc];
        c[nt][0] += t1.x + u1.x; c[nt][1] += t1.y + u1.y;
        c[nt][2] += t2.x + u2.x; c[nt][3] += t2.y + u2.y;
    }

    float m1 = -1e30f, m2 = -1e30f;
#pragma unroll
    for (int nt = 0; nt < 8; nt++) {
        m1 = fmaxf(m1, fmaxf(c[nt][0], c[nt][1]));
        m2 = fmaxf(m2, fmaxf(c[nt][2], c[nt][3]));
    }
#pragma unroll
    for (int off = 1; off < 4; off <<= 1) {
        m1 = fmaxf(m1, __shfl_xor_sync(0xffffffffu, m1, off));
        m2 = fmaxf(m2, __shfl_xor_sync(0xffffffffu, m2, off));
    }
    float s1 = 0.0f, s2 = 0.0f;
#pragma unroll
    for (int nt = 0; nt < 8; nt++) {
        c[nt][0] = __expf(c[nt][0] - m1);
        c[nt][1] = __expf(c[nt][1] - m1);
        c[nt][2] = __expf(c[nt][2] - m2);
        c[nt][3] = __expf(c[nt][3] - m2);
        s1 += c[nt][0] + c[nt][1];
        s2 += c[nt][2] + c[nt][3];
    }
#pragma unroll
    for (int off = 1; off < 4; off <<= 1) {
        s1 += __shfl_xor_sync(0xffffffffu, s1, off);
        s2 += __shfl_xor_sync(0xffffffffu, s2, off);
    }
    const float inv1 = 1.0f / s1, inv2 = 1.0f / s2;
#pragma unroll
    for (int nt = 0; nt < 8; nt++) {
        const int cc = nt * 8 + 2 * tg;
        *(__half2*)&sp[hw][r1][cc] = __floats2half2_rn(c[nt][0] * inv1, c[nt][1] * inv1);
        *(__half2*)&sp[hw][r2][cc] = __floats2half2_rn(c[nt][2] * inv2, c[nt][3] * inv2);
    }
    __syncthreads();

    float o[4][4];
#pragma unroll
    for (int nt = 0; nt < 4; nt++)
#pragma unroll
        for (int r = 0; r < 4; r++) o[nt][r] = 0.0f;

#pragma unroll
    for (int kk = 0; kk < 4; kk++) {
        const int k0 = kk * 16;
        unsigned af[4];
        af[0] = *(const unsigned*)&sp[hw][r1][k0 + 2 * tg];
        af[1] = *(const unsigned*)&sp[hw][r2][k0 + 2 * tg];
        af[2] = *(const unsigned*)&sp[hw][r1][k0 + 2 * tg + 8];
        af[3] = *(const unsigned*)&sp[hw][r2][k0 + 2 * tg + 8];
#pragma unroll
        for (int nt = 0; nt < 4; nt++) {
            unsigned bf[2];
            bf[0] = *(const unsigned*)&svt[hw][nt * 8 + g][k0 + 2 * tg];
            bf[1] = *(const unsigned*)&svt[hw][nt * 8 + g][k0 + 2 * tg + 8];
            mma_f16(o[nt], af, bf);
        }
    }

#pragma unroll
    for (int nt = 0; nt < 4; nt++) {
        const int col = h * HDIM + nt * 8 + 2 * tg;
        *(__half2*)&g_att[((size_t)bw * NTOK + r1) * DIM + col] =
            __floats2half2_rn(o[nt][0], o[nt][1]);
        *(__half2*)&g_att[((size_t)bw * NTOK + r2) * DIM + col] =
            __floats2half2_rn(o[nt][2], o[nt][3]);
    }
}

// ---------------------------------------------------------------------------
extern "C" void kernel_launch(void* const* d_in, const int* in_sizes, int n_in,
                              void* d_out, int out_size)
{
    const float* x      = (const float*)d_in[0];
    const float* mask   = (const float*)d_in[1];
    const float* qkv_w  = (const float*)d_in[2];
    const float* qkv_b  = (const float*)d_in[3];
    const float* btab   = (const float*)d_in[4];
    const float* proj_w = (const float*)d_in[5];
    const float* proj_b = (const float*)d_in[6];
    const int*   ridx   = (const int*)d_in[7];
    float* out = (float*)d_out;

    static bool configured = false;
    if (!configured) {
        cudaFuncSetAttribute(tc_gemm<0>, cudaFuncAttributeMaxDynamicSharedMemorySize, GEMM_SMEM);
        cudaFuncSetAttribute(tc_gemm<1>, cudaFuncAttributeMaxDynamicSharedMemorySize, GEMM_SMEM);
        configured = true;
    }

    __half* xh; cudaGetSymbolAddress((void**)&xh, g_xh);

    // prepasses (merged): weights + bias gather; then x -> fp16
    prep_kernel<<<(WQ4 + WP4 + BT4 + 255) / 256, 256>>>(qkv_w, proj_w, btab, ridx);
    h_kernel<<<(BWTOT * NTOK * DIM / 4 + 255) / 256, 256>>>(x, xh, BWTOT * NTOK * DIM / 4);

    // QKV GEMM (launch #3)
    tc_gemm<0><<<dim3(12, 512), 128, GEMM_SMEM>>>(qkv_b, nullptr);
    // attention (launch #4 -> ncu capture slot)
    attn_kernel<<<BWTOT * (NHEAD / 2), 256>>>(mask);
    // proj GEMM
    tc_gemm<1><<<dim3(4, 512), 128, GEMM_SMEM>>>(proj_b, out);
}

// round 17
// speedup vs baseline: 1.0879x; 1.0802x over previous
#include <cuda_runtime.h>
#include <cuda_fp16.h>
#include <cstdint>

#define NTOK   64
#define DIM    512
#define NHEAD  16
#define HDIM   32
#define NWIN   64
#define BWTOT  1024
#define SCALE  0.17677669529663687f
#define KDIM   512

__device__ __half g_xh [BWTOT * NTOK * DIM];
__device__ __half g_qkv[3 * BWTOT * NHEAD * NTOK * HDIM];
__device__ __half g_att[BWTOT * NTOK * DIM];
__device__ __half g_wq [3 * DIM * DIM];
__device__ __half g_wp [DIM * DIM];
__device__ __half g_bth[NHEAD * NTOK * NTOK];   // bias table fp16, 128 KB (L2-hot)
__device__ __half g_mkh[NWIN * NTOK * NTOK];    // mask fp16, 512 KB (L2-hot)

// ---------------------------------------------------------------------------
__device__ __forceinline__ uint32_t smem_u32(const void* p) {
    uint32_t a;
    asm("{ .reg .u64 t; cvta.to.shared.u64 t, %1; cvt.u32.u64 %0, t; }" : "=r"(a) : "l"(p));
    return a;
}
__device__ __forceinline__ void cp16(uint32_t dst, const void* src) {
    asm volatile("cp.async.cg.shared.global [%0], [%1], 16;" :: "r"(dst), "l"(src));
}
#define CP_COMMIT() asm volatile("cp.async.commit_group;" ::: "memory")
#define CP_WAIT1()  asm volatile("cp.async.wait_group 1;" ::: "memory")
#define CP_WAIT0()  asm volatile("cp.async.wait_group 0;" ::: "memory")

__device__ __forceinline__ void mma_f16(float* c, const unsigned* a, const unsigned* b) {
    asm volatile(
        "mma.sync.aligned.m16n8k16.row.col.f32.f16.f16.f32 "
        "{%0,%1,%2,%3}, {%4,%5,%6,%7}, {%8,%9}, {%0,%1,%2,%3};"
        : "+f"(c[0]), "+f"(c[1]), "+f"(c[2]), "+f"(c[3])
        : "r"(a[0]), "r"(a[1]), "r"(a[2]), "r"(a[3]), "r"(b[0]), "r"(b[1]));
}
__device__ __forceinline__ void ldsm4(unsigned* r, uint32_t a) {
    asm volatile("ldmatrix.sync.aligned.m8n8.x4.shared.b16 {%0,%1,%2,%3}, [%4];"
                 : "=r"(r[0]), "=r"(r[1]), "=r"(r[2]), "=r"(r[3]) : "r"(a));
}
__device__ __forceinline__ void ldsm4t(unsigned* r, uint32_t a) {
    asm volatile("ldmatrix.sync.aligned.m8n8.x4.trans.shared.b16 {%0,%1,%2,%3}, [%4];"
                 : "=r"(r[0]), "=r"(r[1]), "=r"(r[2]), "=r"(r[3]) : "r"(a));
}

// ---------------------------------------------------------------------------
// Prepasses
// ---------------------------------------------------------------------------
__global__ void h_kernel(const float* __restrict__ src, __half* __restrict__ dst, int n4)
{
    const int i = blockIdx.x * blockDim.x + threadIdx.x;
    if (i < n4) {
        float4 v = ((const float4*)src)[i];
        ((__half2*)dst)[2 * i]     = __floats2half2_rn(v.x, v.y);
        ((__half2*)dst)[2 * i + 1] = __floats2half2_rn(v.z, v.w);
    }
}

// merged: weights -> fp16, mask -> fp16, bias gather -> fp16
#define WQ4 (3 * DIM * DIM / 4)          // 196608
#define WP4 (DIM * DIM / 4)              // 65536
#define MK4 (NWIN * NTOK * NTOK / 4)     // 65536
#define BT4 (NHEAD * NTOK * NTOK / 4)    // 16384
__global__ void prep_kernel(const float* __restrict__ qkv_w, const float* __restrict__ proj_w,
                            const float* __restrict__ mask,
                            const float* __restrict__ btab, const int* __restrict__ ridx)
{
    const int i = blockIdx.x * blockDim.x + threadIdx.x;
    if (i < WQ4) {
        const float4 v = ((const float4*)qkv_w)[i];
        ((__half2*)g_wq)[2 * i]     = __floats2half2_rn(v.x, v.y);
        ((__half2*)g_wq)[2 * i + 1] = __floats2half2_rn(v.z, v.w);
    } else if (i < WQ4 + WP4) {
        const int j = i - WQ4;
        const float4 v = ((const float4*)proj_w)[j];
        ((__half2*)g_wp)[2 * j]     = __floats2half2_rn(v.x, v.y);
        ((__half2*)g_wp)[2 * j + 1] = __floats2half2_rn(v.z, v.w);
    } else if (i < WQ4 + WP4 + MK4) {
        const int j = i - WQ4 - WP4;
        const float4 v = ((const float4*)mask)[j];
        ((__half2*)g_mkh)[2 * j]     = __floats2half2_rn(v.x, v.y);
        ((__half2*)g_mkh)[2 * j + 1] = __floats2half2_rn(v.z, v.w);
    } else if (i < WQ4 + WP4 + MK4 + BT4) {
        const int j = (i - WQ4 - WP4 - MK4) * 4;
#pragma unroll
        for (int k = 0; k < 4; k++) {
            const int idx = j + k;
            g_bth[idx] = __float2half(btab[ridx[idx & 4095] * NHEAD + (idx >> 12)]);
        }
    }
}

// ---------------------------------------------------------------------------
// fp16 mma.sync GEMM: 128 threads, 4 warps (2x2 of 64x64), block tile 128x128,
// BK=64, 3-stage cp.async, ldmatrix, XOR swizzle, 2 CTAs/SM.
// ---------------------------------------------------------------------------
#define BKH 64
#define STG 3
#define STAGE_ROWS 128
#define GEMM_SMEM (STG * 2 * STAGE_ROWS * BKH * 2)   // 98304

template<int MODE>
__global__ __launch_bounds__(128, 2) void tc_gemm(
    const float* __restrict__ bias, float* __restrict__ C)
{
    extern __shared__ char smh[];
    const uint32_t sA = smem_u32(smh);
    const uint32_t sB = sA + STG * STAGE_ROWS * 128;

    const int tid  = threadIdx.x;
    const int warp = tid >> 5;
    const int lane = tid & 31;
    const int g    = lane >> 2;
    const int tg   = lane & 3;
    const int wm   = (warp >> 1) * 64;
    const int wn   = (warp & 1) * 64;
    const int bm = blockIdx.y, bn = blockIdx.x;

    const __half* Ap = (MODE == 0 ? g_xh : g_att) + (size_t)bm * 128 * KDIM;
    const __half* Bp = (MODE == 0 ? g_wq : g_wp) + (size_t)bn * 128 * KDIM;

    const int mi    = lane >> 3;
    const int l7    = lane & 7;
    const int arow  = wm + (mi & 1) * 8 + l7;
    const int achk  = mi >> 1;
    const int brow  = wn + (mi >> 1) * 8 + l7;
    const int bchk  = mi & 1;

    float acc[4][8][4];
#pragma unroll
    for (int i = 0; i < 4; i++)
#pragma unroll
        for (int j = 0; j < 8; j++)
#pragma unroll
            for (int r = 0; r < 4; r++) acc[i][j][r] = 0.0f;

    auto issue = [&](int ks) {
        const int k0 = ks * BKH;
        const int buf = ks % STG;
#pragma unroll
        for (int t = 0; t < 8; t++) {
            const int id = tid + t * 128;
            const int r = id >> 3, c = id & 7;
            const uint32_t off = ((buf * STAGE_ROWS + r) * 8 + (c ^ (r & 7))) * 16;
            cp16(sA + off, Ap + (size_t)r * KDIM + k0 + c * 8);
            cp16(sB + off, Bp + (size_t)r * KDIM + k0 + c * 8);
        }
        CP_COMMIT();
    };

    issue(0); issue(1);
    for (int ks = 0; ks < 8; ks++) {
        if (ks < 7) { CP_WAIT1(); } else { CP_WAIT0(); }
        __syncthreads();
        if (ks < 6) issue(ks + 2);

        const int bo = (ks % STG) * STAGE_ROWS;
#pragma unroll
        for (int kk = 0; kk < 4; kk++) {
            unsigned af[4][4], bf[8][2];
#pragma unroll
            for (int mt = 0; mt < 4; mt++) {
                const int r = bo + arow + mt * 16;
                ldsm4(af[mt], sA + (r * 8 + ((kk * 2 + achk) ^ l7)) * 16);
            }
#pragma unroll
            for (int j = 0; j < 4; j++) {
                const int r = bo + brow + j * 16;
                ldsm4(&bf[2 * j][0], sB + (r * 8 + ((kk * 2 + bchk) ^ l7)) * 16);
            }
#pragma unroll
            for (int mt = 0; mt < 4; mt++)
#pragma unroll
                for (int nt = 0; nt < 8; nt++)
                    mma_f16(acc[mt][nt], af[mt], bf[nt]);
        }
    }

#pragma unroll
    for (int mt = 0; mt < 4; mt++) {
#pragma unroll
        for (int nt = 0; nt < 8; nt++) {
#pragma unroll
            for (int half = 0; half < 2; half++) {
                const int m   = bm * 128 + wm + mt * 16 + g + half * 8;
                const int col = bn * 128 + wn + nt * 8 + 2 * tg;
                const float v0 = acc[mt][nt][half * 2 + 0] + bias[col];
                const float v1 = acc[mt][nt][half * 2 + 1] + bias[col + 1];
                if (MODE == 0) {
                    const int part = col >> 9;
                    const int h    = (col >> 5) & 15;
                    const int d    = col & 31;
                    const int bw   = m >> 6;
                    const int n    = m & 63;
                    __half* dst = &g_qkv[(((size_t)part * BWTOT + bw) * NHEAD + h)
                                         * (NTOK * HDIM) + n * HDIM + d];
                    *(__half2*)dst = __floats2half2_rn(v0, v1);
                } else {
                    *(float2*)&C[(size_t)m * DIM + col] = make_float2(v0, v1);
                }
            }
        }
    }
}

// ---------------------------------------------------------------------------
// fp16 tensor-core attention v2: one block per (window, head-pair), 256 thr.
// cp.async fills, ldmatrix fragments (trans for V), SCALE folded in epilogue,
// fp16 bias/mask tables.
// smem (halfs): sq[2][64][40] | sk[2][64][40] | sv[2][64][40] | sp[2][64][72]
// ---------------------------------------------------------------------------
#define ATT_SMEM 49152

__global__ __launch_bounds__(256) void attn_kernel()
{
    extern __shared__ __half sm[];
    const int tid  = threadIdx.x;
    const int hw   = tid >> 7;
    const int ltid = tid & 127;
    const int warp = ltid >> 5;
    const int lane = tid & 31;
    const int g    = lane >> 2;
    const int tg   = lane & 3;
    const int quad = lane >> 3;
    const int l7   = lane & 7;
    const int bw = blockIdx.x >> 3;
    const int h  = (blockIdx.x & 7) * 2 + hw;

    const uint32_t squ = smem_u32(sm) + hw * 5120;
    const uint32_t sku = squ + 10240;
    const uint32_t svu = sku + 10240;
    const uint32_t spu = smem_u32(sm) + 30720 + hw * 9216;

    const __half* qp = g_qkv + ((size_t)bw * NHEAD + h) * (NTOK * HDIM);
    const __half* kp = qp + (size_t)BWTOT * NHEAD * NTOK * HDIM;
    const __half* vp = kp + (size_t)BWTOT * NHEAD * NTOK * HDIM;

    // fill q,k,v: 64 rows x 4 chunks of 16B each; pitch 40 halfs
#pragma unroll
    for (int j = 0; j < 2; j++) {
        const int ch = ltid * 2 + j;             // 0..255
        const int r = ch >> 2, cb = (ch & 3) * 8;
        const uint32_t doff = (r * 40 + cb) * 2;
        cp16(squ + doff, qp + r * 32 + cb);
        cp16(sku + doff, kp + r * 32 + cb);
        cp16(svu + doff, vp + r * 32 + cb);
    }
    CP_COMMIT(); CP_WAIT0();
    __syncthreads();

    const int row0 = warp * 16;
    const int r1 = row0 + g, r2 = row0 + g + 8;

    // ---- S = Q @ K^T (unscaled) ----
    float c[8][4];
#pragma unroll
    for (int nt = 0; nt < 8; nt++)
#pragma unroll
        for (int r = 0; r < 4; r++) c[nt][r] = 0.0f;

#pragma unroll
    for (int kk = 0; kk < 2; kk++) {
        unsigned af[4];
        ldsm4(af, squ + ((row0 + (quad & 1) * 8 + l7) * 40 + kk * 16 + (quad >> 1) * 8) * 2);
#pragma unroll
        for (int np = 0; np < 4; np++) {
            unsigned bf[4];
            ldsm4(bf, sku + (((2 * np + (quad >> 1)) * 8 + l7) * 40 + kk * 16 + (quad & 1) * 8) * 2);
            mma_f16(c[2 * np], af, bf);
            mma_f16(c[2 * np + 1], af, bf + 2);
        }
    }

    // ---- scale + bias + mask (fp16 tables, L2-hot) ----
    const __half* btp = g_bth + (size_t)h * 4096;
    const __half* mkp = g_mkh + (size_t)(bw & (NWIN - 1)) * 4096;
#pragma unroll
    for (int nt = 0; nt < 8; nt++) {
        const int cc = nt * 8 + 2 * tg;
        float2 t1 = __half22float2(*(const __half2*)&btp[r1 * 64 + cc]);
        float2 t2 = __half22float2(*(const __half2*)&btp[r2 * 64 + cc]);
        float2 u1 = __half22float2(*(const __half2*)&mkp[r1 * 64 + cc]);
        float2 u2 = __half22float2(*(const __half2*)&mkp[r2 * 64 + cc]);
        c[nt][0] = fmaf(c[nt][0], SCALE, t1.x + u1.x);
        c[nt][1] = fmaf(c[nt][1], SCALE, t1.y + u1.y);
        c[nt][2] = fmaf(c[nt][2], SCALE, t2.x + u2.x);
        c[nt][3] = fmaf(c[nt][3], SCALE, t2.y + u2.y);
    }

    // ---- softmax ----
    float m1 = -1e30f, m2 = -1e30f;
#pragma unroll
    for (int nt = 0; nt < 8; nt++) {
        m1 = fmaxf(m1, fmaxf(c[nt][0], c[nt][1]));
        m2 = fmaxf(m2, fmaxf(c[nt][2], c[nt][3]));
    }
#pragma unroll
    for (int off = 1; off < 4; off <<= 1) {
        m1 = fmaxf(m1, __shfl_xor_sync(0xffffffffu, m1, off));
        m2 = fmaxf(m2, __shfl_xor_sync(0xffffffffu, m2, off));
    }
    float s1 = 0.0f, s2 = 0.0f;
#pragma unroll
    for (int nt = 0; nt < 8; nt++) {
        c[nt][0] = __expf(c[nt][0] - m1);
        c[nt][1] = __expf(c[nt][1] - m1);
        c[nt][2] = __expf(c[nt][2] - m2);
        c[nt][3] = __expf(c[nt][3] - m2);
        s1 += c[nt][0] + c[nt][1];
        s2 += c[nt][2] + c[nt][3];
    }
#pragma unroll
    for (int off = 1; off < 4; off <<= 1) {
        s1 += __shfl_xor_sync(0xffffffffu, s1, off);
        s2 += __shfl_xor_sync(0xffffffffu, s2, off);
    }
    const float inv1 = 1.0f / s1, inv2 = 1.0f / s2;
#pragma unroll
    for (int nt = 0; nt < 8; nt++) {
        const int cc = nt * 8 + 2 * tg;
        __half2 p1 = __floats2half2_rn(c[nt][0] * inv1, c[nt][1] * inv1);
        __half2 p2 = __floats2half2_rn(c[nt][2] * inv2, c[nt][3] * inv2);
        asm volatile("st.shared.b32 [%0], %1;" :: "r"(spu + (r1 * 72 + cc) * 2), "r"(*(unsigned*)&p1));
        asm volatile("st.shared.b32 [%0], %1;" :: "r"(spu + (r2 * 72 + cc) * 2), "r"(*(unsigned*)&p2));
    }
    __syncthreads();

    // ---- O = P @ V  (V row-major, B fragments via ldmatrix.trans) ----
    float o[4][4];
#pragma unroll
    for (int nt = 0; nt < 4; nt++)
#pragma unroll
        for (int r = 0; r < 4; r++) o[nt][r] = 0.0f;

#pragma unroll
    for (int kk = 0; kk < 4; kk++) {
        unsigned af[4];
        ldsm4(af, spu + ((row0 + (quad & 1) * 8 + l7) * 72 + kk * 16 + (quad >> 1) * 8) * 2);
#pragma unroll
        for (int np = 0; np < 2; np++) {
            unsigned bf[4];
            ldsm4t(bf, svu + ((kk * 16 + (quad & 1) * 8 + l7) * 40 + (2 * np + (quad >> 1)) * 8) * 2);
            mma_f16(o[2 * np], af, bf);
            mma_f16(o[2 * np + 1], af, bf + 2);
        }
    }

#pragma unroll
    for (int nt = 0; nt < 4; nt++) {
        const int col = h * HDIM + nt * 8 + 2 * tg;
        *(__half2*)&g_att[((size_t)bw * NTOK + r1) * DIM + col] =
            __floats2half2_rn(o[nt][0], o[nt][1]);
        *(__half2*)&g_att[((size_t)bw * NTOK + r2) * DIM + col] =
            __floats2half2_rn(o[nt][2], o[nt][3]);
    }
}

// ---------------------------------------------------------------------------
extern "C" void kernel_launch(void* const* d_in, const int* in_sizes, int n_in,
                              void* d_out, int out_size)
{
    const float* x      = (const float*)d_in[0];
    const float* mask   = (const float*)d_in[1];
    const float* qkv_w  = (const float*)d_in[2];
    const float* qkv_b  = (const float*)d_in[3];
    const float* btab   = (const float*)d_in[4];
    const float* proj_w = (const float*)d_in[5];
    const float* proj_b = (const float*)d_in[6];
    const int*   ridx   = (const int*)d_in[7];
    float* out = (float*)d_out;

    static bool configured = false;
    if (!configured) {
        cudaFuncSetAttribute(tc_gemm<0>, cudaFuncAttributeMaxDynamicSharedMemorySize, GEMM_SMEM);
        cudaFuncSetAttribute(tc_gemm<1>, cudaFuncAttributeMaxDynamicSharedMemorySize, GEMM_SMEM);
        cudaFuncSetAttribute(attn_kernel, cudaFuncAttributeMaxDynamicSharedMemorySize, ATT_SMEM);
        configured = true;
    }

    __half* xh; cudaGetSymbolAddress((void**)&xh, g_xh);

    // prepasses
    prep_kernel<<<(WQ4 + WP4 + MK4 + BT4 + 255) / 256, 256>>>(qkv_w, proj_w, mask, btab, ridx);
    h_kernel<<<(BWTOT * NTOK * DIM / 4 + 255) / 256, 256>>>(x, xh, BWTOT * NTOK * DIM / 4);

    // QKV GEMM
    tc_gemm<0><<<dim3(12, 512), 128, GEMM_SMEM>>>(qkv_b, nullptr);
    // attention (capture slot)
    attn_kernel<<<BWTOT * (NHEAD / 2), 256, ATT_SMEM>>>();
    // proj GEMM
    tc_gemm<1><<<dim3(4, 512), 128, GEMM_SMEM>>>(proj_b, out);
}